// round 8
// baseline (speedup 1.0000x reference)
#include <cuda_runtime.h>
#include <cuda_bf16.h>
#include <cstdint>

// Problem dims: B=256, T=256, D=96, H=6, E=16, DFF=384
#define NTOK 65536              // B*T

// ---------------- scratch (device globals; no allocations) ----------------
__device__ __nv_bfloat16 g_h [NTOK * 96];    // attn concat output (bf16)
__device__ __nv_bfloat16 g_q [NTOK * 96];    // [B*H, T, E] bf16
__device__ __nv_bfloat16 g_k [NTOK * 96];
__device__ __nv_bfloat16 g_v [NTOK * 96];
__device__ float         g_x1[NTOK * 96];    // residual after attention branch
__device__ __nv_bfloat16 g_f [NTOK * 384];   // FF hidden (bf16)
__device__ float         g_n1[NTOK * 96];    // precomputed noise1
__device__ float         g_n2[NTOK * 96];    // precomputed noise2

// pre-converted bf16 weights (k-major [k][n] layouts)
__device__ __nv_bfloat16 g_wq[96 * 96];
__device__ __nv_bfloat16 g_wk[96 * 96];
__device__ __nv_bfloat16 g_wv[96 * 96];
__device__ __nv_bfloat16 g_wp[96 * 96];
__device__ __nv_bfloat16 g_w1c[96 * 384];
__device__ __nv_bfloat16 g_w2c[384 * 96];

// ---------------- bf16 mma + ldmatrix + cp.async helpers ----------------
__device__ __forceinline__ void ldsm4(unsigned (&r)[4], unsigned addr) {
  asm volatile("ldmatrix.sync.aligned.m8n8.x4.shared.b16 {%0,%1,%2,%3}, [%4];"
               : "=r"(r[0]), "=r"(r[1]), "=r"(r[2]), "=r"(r[3]) : "r"(addr));
}
__device__ __forceinline__ void ldsm4t(unsigned (&r)[4], unsigned addr) {
  asm volatile("ldmatrix.sync.aligned.m8n8.x4.trans.shared.b16 {%0,%1,%2,%3}, [%4];"
               : "=r"(r[0]), "=r"(r[1]), "=r"(r[2]), "=r"(r[3]) : "r"(addr));
}
__device__ __forceinline__ void mma_bf16(float (&d)[4], const unsigned (&a)[4], unsigned b0, unsigned b1) {
  asm volatile("mma.sync.aligned.m16n8k16.row.col.f32.bf16.bf16.f32 "
               "{%0,%1,%2,%3}, {%4,%5,%6,%7}, {%8,%9}, {%0,%1,%2,%3};"
               : "+f"(d[0]), "+f"(d[1]), "+f"(d[2]), "+f"(d[3])
               : "r"(a[0]), "r"(a[1]), "r"(a[2]), "r"(a[3]), "r"(b0), "r"(b1));
}
__device__ __forceinline__ unsigned s2u(const void* p) {
  return (unsigned)__cvta_generic_to_shared(p);
}
__device__ __forceinline__ void cp16(unsigned dst, const void* src) {
  asm volatile("cp.async.cg.shared.global [%0], [%1], 16;" :: "r"(dst), "l"(src));
}
#define CP_COMMIT asm volatile("cp.async.commit_group;")
#define CP_WAIT(N) asm volatile("cp.async.wait_group %0;" :: "n"(N))
__device__ __forceinline__ unsigned pack_bf2(float lo, float hi) {
  __nv_bfloat162 h = __float22bfloat162_rn(make_float2(lo, hi));
  return *reinterpret_cast<unsigned*>(&h);
}

// ---------------- JAX threefry-2x32 (20 rounds) ----------------
__host__ __device__ __forceinline__ void tf2x32(unsigned k0, unsigned k1,
                                                unsigned x0, unsigned x1,
                                                unsigned &o0, unsigned &o1) {
  unsigned k2 = k0 ^ k1 ^ 0x1BD11BDAu;
  unsigned v0 = x0 + k0, v1 = x1 + k1;
#define TFR(r) { v0 += v1; v1 = (v1 << (r)) | (v1 >> (32 - (r))); v1 ^= v0; }
  TFR(13) TFR(15) TFR(26) TFR(6)   v0 += k1; v1 += k2 + 1u;
  TFR(17) TFR(29) TFR(16) TFR(24)  v0 += k2; v1 += k0 + 2u;
  TFR(13) TFR(15) TFR(26) TFR(6)   v0 += k0; v1 += k1 + 3u;
  TFR(17) TFR(29) TFR(16) TFR(24)  v0 += k1; v1 += k2 + 4u;
  TFR(13) TFR(15) TFR(26) TFR(6)   v0 += k2; v1 += k0 + 5u;
#undef TFR
  o0 = v0; o1 = v1;
}

// Giles (2012) single-precision erfinv: one MUFU log + ~9 fma per path.
__device__ __forceinline__ float fast_erfinv(float x) {
  float w = -__logf((1.0f - x) * (1.0f + x));
  float p;
  if (w < 5.0f) {
    w -= 2.5f;
    p = 2.81022636e-08f;
    p = fmaf(p, w, 3.43273939e-07f);
    p = fmaf(p, w, -3.5233877e-06f);
    p = fmaf(p, w, -4.39150654e-06f);
    p = fmaf(p, w, 0.00021858087f);
    p = fmaf(p, w, -0.00125372503f);
    p = fmaf(p, w, -0.00417768164f);
    p = fmaf(p, w, 0.246640727f);
    p = fmaf(p, w, 1.50140941f);
  } else {
    w = sqrtf(w) - 3.0f;
    p = -0.000200214257f;
    p = fmaf(p, w, 0.000100950558f);
    p = fmaf(p, w, 0.00134934322f);
    p = fmaf(p, w, -0.00367342844f);
    p = fmaf(p, w, 0.00573950773f);
    p = fmaf(p, w, -0.0076224613f);
    p = fmaf(p, w, 0.00943887047f);
    p = fmaf(p, w, 1.00167406f);
    p = fmaf(p, w, 2.83297682f);
  }
  return p * x;
}

__device__ __forceinline__ float jax_noise(unsigned k0, unsigned k1, unsigned idx) {
  unsigned o0, o1;
  tf2x32(k0, k1, 0u, idx, o0, o1);
  unsigned bits = o0 ^ o1;
  float u = __uint_as_float((bits >> 9) | 0x3f800000u) - 1.0f;
  const float lo = -0.99999994f;
  float val = u * 1.99999994f + lo;
  val = fmaxf(lo, val);
  return 0.1f * (1.4142135381698608f * fast_erfinv(val));
}

// ---------------- weight prep: fp32 -> bf16, gather into [k][n] ----------------
__global__ void __launch_bounds__(256) prep_kernel(const float* __restrict__ Wq,
                                                   const float* __restrict__ Wk,
                                                   const float* __restrict__ Wv,
                                                   const float* __restrict__ Wp,
                                                   const float* __restrict__ W1,
                                                   const float* __restrict__ W2) {
  int i = blockIdx.x * 256 + threadIdx.x;
  if (i < 9216) {
    int r = i / 96, c = i % 96;
    int h = c >> 4, e = c & 15;
    int s = h * 1536 + r * 16 + e;
    g_wq[i] = __float2bfloat16_rn(Wq[s]);
    g_wk[i] = __float2bfloat16_rn(Wk[s]);
    g_wv[i] = __float2bfloat16_rn(Wv[s]);
    g_wp[i] = __float2bfloat16_rn(Wp[i]);
  } else if (i < 9216 + 36864) {
    int j = i - 9216;
    g_w1c[j] = __float2bfloat16_rn(W1[j]);
  } else if (i < 9216 + 2 * 36864) {
    int j = i - 9216 - 36864;
    g_w2c[j] = __float2bfloat16_rn(W2[j]);
  }
}

// ============ smem: A 128x96 bf16 stride 136; B double-buffered 96x96 ============
#define SASTRIDE 136
#define A_ELEMS (128 * SASTRIDE)
#define B_ELEMS (96 * SASTRIDE)
#define SMEM_BYTES ((A_ELEMS + 2 * B_ELEMS) * 2)

#define GEMM_PROLOG \
  extern __shared__ __align__(16) char smraw[]; \
  __nv_bfloat16* sm_a  = reinterpret_cast<__nv_bfloat16*>(smraw); \
  __nv_bfloat16* sm_b0 = sm_a + A_ELEMS; \
  __nv_bfloat16* sm_b1 = sm_b0 + B_ELEMS; \
  int tid = threadIdx.x; \
  int warp = tid >> 5, lane = tid & 31; \
  int wr = warp / 3, wc = warp % 3; \
  int gid = lane >> 2, tig = lane & 3; \
  int lrow = lane & 15, lsel = lane >> 4; \
  int row0 = blockIdx.x * 128; \
  unsigned aB0 = s2u(&sm_a[(wr * 32 + lrow) * SASTRIDE + lsel * 8]); \
  unsigned aB1 = aB0 + 16 * SASTRIDE * 2;

#define CPA_B(BUF, SRC, LD, OFF) \
  _Pragma("unroll") \
  for (int i = 0; i < 3; i++) { \
    int c = tid + i * 384; int r = c / 12, q = c % 12; \
    cp16(s2u(&(BUF)[r * SASTRIDE + q * 8]), (SRC) + r * (LD) + (OFF) + q * 8); \
  }

#define CPA_A(SRC, LD, OFF) \
  _Pragma("unroll") \
  for (int i = 0; i < 4; i++) { \
    int c = tid + i * 384; int r = c / 12, q = c % 12; \
    cp16(s2u(&sm_a[r * SASTRIDE + q * 8]), (SRC) + (size_t)(row0 + r) * (LD) + (OFF) + q * 8); \
  }

#define LN_TO_SMEM(SRC, G, Bv) \
  { \
    float g0 = (G)[lane], g1 = (G)[lane + 32], g2 = (G)[lane + 64]; \
    float b0 = (Bv)[lane], b1 = (Bv)[lane + 32], b2 = (Bv)[lane + 64]; \
    for (int r = warp; r < 128; r += 12) { \
      const float* xr = (SRC) + (size_t)(row0 + r) * 96; \
      float v0 = xr[lane], v1 = xr[lane + 32], v2 = xr[lane + 64]; \
      float s = v0 + v1 + v2, sq = v0 * v0 + v1 * v1 + v2 * v2; \
      _Pragma("unroll") \
      for (int o = 16; o; o >>= 1) { \
        s  += __shfl_xor_sync(0xffffffffu, s, o); \
        sq += __shfl_xor_sync(0xffffffffu, sq, o); \
      } \
      float mu = s * (1.0f / 96.0f); \
      float rs = rsqrtf(sq * (1.0f / 96.0f) - mu * mu + 1e-5f); \
      sm_a[r * SASTRIDE + lane]      = __float2bfloat16_rn((v0 - mu) * rs * g0 + b0); \
      sm_a[r * SASTRIDE + lane + 32] = __float2bfloat16_rn((v1 - mu) * rs * g1 + b1); \
      sm_a[r * SASTRIDE + lane + 64] = __float2bfloat16_rn((v2 - mu) * rs * g2 + b2); \
    } \
  }

#define MMA_K96_BF16(BB) \
  { \
    unsigned bb0 = s2u(&(BB)[lrow * SASTRIDE + wc * 32 + lsel * 8]); \
    unsigned bb1 = bb0 + 16 * 2; \
    _Pragma("unroll") \
    for (int kc = 0; kc < 6; kc++) { \
      unsigned a[2][4], bt[2][4]; \
      ldsm4 (a[0],  aB0 + kc * 32); \
      ldsm4 (a[1],  aB1 + kc * 32); \
      ldsm4t(bt[0], bb0 + kc * (16 * SASTRIDE * 2)); \
      ldsm4t(bt[1], bb1 + kc * (16 * SASTRIDE * 2)); \
      _Pragma("unroll") \
      for (int mt = 0; mt < 2; mt++) \
        _Pragma("unroll") \
        for (int nt = 0; nt < 4; nt++) \
          mma_bf16(acc[mt][nt], a[mt], bt[nt >> 1][(nt & 1) * 2], bt[nt >> 1][(nt & 1) * 2 + 1]); \
    } \
  }

// ---- fused LN1 + QKV: B tiles double-buffered; bf16 q/k/v out ----
__global__ void __launch_bounds__(384, 2) qkv_kernel(const float* __restrict__ x,
                                                     const float* __restrict__ ln1g,
                                                     const float* __restrict__ ln1b) {
  GEMM_PROLOG
  CPA_B(sm_b0, g_wq, 96, 0)
  CP_COMMIT;
  LN_TO_SMEM(x, ln1g, ln1b)
  for (int w = 0; w < 3; w++) {
    CP_WAIT(0);
    __syncthreads();
    if (w == 0) { CPA_B(sm_b1, g_wk, 96, 0) CP_COMMIT; }
    if (w == 1) { CPA_B(sm_b0, g_wv, 96, 0) CP_COMMIT; }
    float acc[2][4][4] = {};
    if (w & 1) { MMA_K96_BF16(sm_b1) } else { MMA_K96_BF16(sm_b0) }
    __nv_bfloat16* Out = (w == 0) ? g_q : (w == 1) ? g_k : g_v;
#pragma unroll
    for (int mt = 0; mt < 2; mt++)
#pragma unroll
      for (int nt = 0; nt < 4; nt++) {
        int r0 = row0 + wr * 32 + mt * 16 + gid;
        int c0 = wc * 32 + nt * 8 + 2 * tig;
        int h = c0 >> 4, e = c0 & 15;
#pragma unroll
        for (int rr = 0; rr < 2; rr++) {
          int tok = r0 + rr * 8;
          int b_ = tok >> 8, t_ = tok & 255;
          *reinterpret_cast<__nv_bfloat162*>(&Out[((b_ * 6 + h) * 256 + t_) * 16 + e]) =
              __float22bfloat162_rn(make_float2(acc[mt][nt][2 * rr], acc[mt][nt][2 * rr + 1]));
        }
      }
  }
}

// ---- tensor-core flash attention + noise1 generation ----
__global__ void __launch_bounds__(256) attn_kernel(unsigned nk0, unsigned nk1v) {
  int bh = blockIdx.x;
  __shared__ __align__(16) __nv_bfloat16 qs[256 * 24];
  __shared__ __align__(16) __nv_bfloat16 ks[256 * 24];
  __shared__ __align__(16) __nv_bfloat16 vs[256 * 24];
  const __nv_bfloat16* qb = g_q + (size_t)bh * 4096;
  const __nv_bfloat16* kb = g_k + (size_t)bh * 4096;
  const __nv_bfloat16* vb = g_v + (size_t)bh * 4096;
  int tid = threadIdx.x;
#pragma unroll
  for (int i = 0; i < 2; i++) {
    int idx = tid + i * 256;
    int r = idx >> 1, half = idx & 1;
    cp16(s2u(&qs[r * 24 + half * 8]), qb + r * 16 + half * 8);
    cp16(s2u(&ks[r * 24 + half * 8]), kb + r * 16 + half * 8);
    cp16(s2u(&vs[r * 24 + half * 8]), vb + r * 16 + half * 8);
  }
  CP_COMMIT;

  // noise1 generation: 4096 elems per block, hides cp.async latency + fills
  // idle issue slots of the MUFU/tensor-bound attention work below.
  {
    unsigned base = (unsigned)bh * 4096u + (unsigned)tid;
#pragma unroll 4
    for (int i = 0; i < 16; i++) {
      unsigned idx = base + (unsigned)(i * 256);
      g_n1[idx] = jax_noise(nk0, nk1v, idx);
    }
  }

  CP_WAIT(0);
  __syncthreads();
  int warp = tid >> 5, lane = tid & 31;
  int gid = lane >> 2, tig = lane & 3;
  int lrow = lane & 15, lsel = lane >> 4;
  int r0 = warp * 32;

  unsigned qa[2][4];
  ldsm4(qa[0], s2u(&qs[(r0 + lrow) * 24 + lsel * 8]));
  ldsm4(qa[1], s2u(&qs[(r0 + 16 + lrow) * 24 + lsel * 8]));

  float o[2][2][4] = {};
  float lsum[2][2] = {};
  int krow_off = (lane & 7) + ((lane >> 4) << 3);
  int khalf = (lane >> 3) & 1;
  int nkb = (r0 >> 6) + 1;

  for (int kbk = 0; kbk < nkb; kbk++) {
    int cb = kbk * 64;
    unsigned kf[4][4];
#pragma unroll
    for (int i = 0; i < 4; i++)
      ldsm4(kf[i], s2u(&ks[(cb + i * 16 + krow_off) * 24 + khalf * 8]));
    unsigned pa[2][4][4];
#pragma unroll
    for (int mt = 0; mt < 2; mt++) {
      int ra = r0 + mt * 16 + gid, rb = ra + 8;
      float s[8][4];
#pragma unroll
      for (int nt = 0; nt < 8; nt++) {
        s[nt][0] = s[nt][1] = s[nt][2] = s[nt][3] = 0.0f;
        mma_bf16(s[nt], qa[mt], kf[nt >> 1][(nt & 1) * 2], kf[nt >> 1][(nt & 1) * 2 + 1]);
      }
#pragma unroll
      for (int nt = 0; nt < 8; nt++) {
        int c0 = cb + nt * 8 + 2 * tig;
        float p0 = (c0     <= ra) ? __expf(s[nt][0] * 0.25f) : 0.0f;
        float p1 = (c0 + 1 <= ra) ? __expf(s[nt][1] * 0.25f) : 0.0f;
        float p2 = (c0     <= rb) ? __expf(s[nt][2] * 0.25f) : 0.0f;
        float p3 = (c0 + 1 <= rb) ? __expf(s[nt][3] * 0.25f) : 0.0f;
        lsum[mt][0] += p0 + p1;
        lsum[mt][1] += p2 + p3;
        int kc = nt >> 1, hi = nt & 1;
        pa[mt][kc][hi * 2 + 0] = pack_bf2(p0, p1);
        pa[mt][kc][hi * 2 + 1] = pack_bf2(p2, p3);
      }
    }
#pragma unroll
    for (int kc = 0; kc < 4; kc++) {
      unsigned vt[4];
      ldsm4t(vt, s2u(&vs[(cb + kc * 16 + lrow) * 24 + lsel * 8]));
#pragma unroll
      for (int mt = 0; mt < 2; mt++) {
        mma_bf16(o[mt][0], pa[mt][kc], vt[0], vt[1]);
        mma_bf16(o[mt][1], pa[mt][kc], vt[2], vt[3]);
      }
    }
  }
#pragma unroll
  for (int mt = 0; mt < 2; mt++)
#pragma unroll
    for (int rr = 0; rr < 2; rr++) {
      float v = lsum[mt][rr];
      v += __shfl_xor_sync(0xffffffffu, v, 1);
      v += __shfl_xor_sync(0xffffffffu, v, 2);
      lsum[mt][rr] = 1.0f / v;
    }
  int b_ = bh / 6, h_ = bh % 6;
#pragma unroll
  for (int mt = 0; mt < 2; mt++) {
    int ra = r0 + mt * 16 + gid, rb = ra + 8;
#pragma unroll
    for (int nt = 0; nt < 2; nt++) {
      int c = nt * 8 + 2 * tig;
      *reinterpret_cast<__nv_bfloat162*>(&g_h[((size_t)(b_ * 256 + ra)) * 96 + h_ * 16 + c]) =
          __float22bfloat162_rn(make_float2(o[mt][nt][0] * lsum[mt][0], o[mt][nt][1] * lsum[mt][0]));
      *reinterpret_cast<__nv_bfloat162*>(&g_h[((size_t)(b_ * 256 + rb)) * 96 + h_ * 16 + c]) =
          __float22bfloat162_rn(make_float2(o[mt][nt][2] * lsum[mt][1], o[mt][nt][3] * lsum[mt][1]));
    }
  }
}

// ---- projection + residual + precomputed noise1 ----
__global__ void __launch_bounds__(384, 2) proj_kernel(const float* __restrict__ bp,
                                                      const float* __restrict__ x) {
  GEMM_PROLOG
  CPA_A(g_h, 96, 0)
  CPA_B(sm_b0, g_wp, 96, 0)
  CP_COMMIT;
  CP_WAIT(0);
  __syncthreads();
  float acc[2][4][4] = {};
  MMA_K96_BF16(sm_b0)
#pragma unroll
  for (int mt = 0; mt < 2; mt++)
#pragma unroll
    for (int nt = 0; nt < 4; nt++) {
      int r0 = row0 + wr * 32 + mt * 16 + gid;
      int c0 = wc * 32 + nt * 8 + 2 * tig;
      float bp0 = bp[c0], bp1 = bp[c0 + 1];
#pragma unroll
      for (int rr = 0; rr < 2; rr++) {
        int i0 = (r0 + rr * 8) * 96 + c0;
        float2 xv = *reinterpret_cast<const float2*>(&x[i0]);
        float2 nv = *reinterpret_cast<const float2*>(&g_n1[i0]);
        *reinterpret_cast<float2*>(&g_x1[i0]) =
            make_float2(xv.x + acc[mt][nt][2 * rr]     + bp0 + nv.x,
                        xv.y + acc[mt][nt][2 * rr + 1] + bp1 + nv.y);
      }
    }
}

// ---- fused LN2 + FF1 (4 col groups) + noise2 generation ----
__global__ void __launch_bounds__(384, 2) ff1_kernel(const float* __restrict__ b1,
                                                     const float* __restrict__ ln2g,
                                                     const float* __restrict__ ln2b,
                                                     unsigned nk0, unsigned nk1v) {
  GEMM_PROLOG
  CPA_B(sm_b0, g_w1c, 384, 0)
  CP_COMMIT;
  LN_TO_SMEM(g_x1, ln2g, ln2b)
  // noise2 generation: 12288 elems per block, fills idle issue slots
  {
    unsigned base = (unsigned)blockIdx.x * 12288u + (unsigned)tid;
#pragma unroll 4
    for (int i = 0; i < 32; i++) {
      unsigned idx = base + (unsigned)(i * 384);
      g_n2[idx] = jax_noise(nk0, nk1v, idx);
    }
  }
  for (int grp = 0; grp < 4; grp++) {
    int co = grp * 96;
    CP_WAIT(0);
    __syncthreads();
    if (grp < 3) {
      if (grp & 1) { CPA_B(sm_b0, g_w1c, 384, co + 96) }
      else         { CPA_B(sm_b1, g_w1c, 384, co + 96) }
      CP_COMMIT;
    }
    float acc[2][4][4] = {};
    if (grp & 1) { MMA_K96_BF16(sm_b1) } else { MMA_K96_BF16(sm_b0) }
#pragma unroll
    for (int mt = 0; mt < 2; mt++)
#pragma unroll
      for (int nt = 0; nt < 4; nt++) {
        int r0 = row0 + wr * 32 + mt * 16 + gid;
        int c0 = wc * 32 + nt * 8 + 2 * tig;
        float bb0 = b1[co + c0], bb1 = b1[co + c0 + 1];
#pragma unroll
        for (int rr = 0; rr < 2; rr++) {
          int tok = r0 + rr * 8;
          *reinterpret_cast<__nv_bfloat162*>(&g_f[(size_t)tok * 384 + co + c0]) =
              __float22bfloat162_rn(make_float2(fmaxf(acc[mt][nt][2 * rr] + bb0, 0.0f),
                                                fmaxf(acc[mt][nt][2 * rr + 1] + bb1, 0.0f)));
        }
      }
  }
}

// ---- FF2 + residual + precomputed noise2 -> out ----
__global__ void __launch_bounds__(384, 2) ff2_kernel(const float* __restrict__ b2,
                                                     float* __restrict__ out) {
  GEMM_PROLOG
  CPA_B(sm_b0, g_w2c, 96, 0)
  CP_COMMIT;
  float acc[2][4][4] = {};
#pragma unroll
  for (int g = 0; g < 4; g++) {
    __syncthreads();
    CPA_A(g_f, 384, g * 96)
    CP_COMMIT;
    if (g < 3) {
      const __nv_bfloat16* src = g_w2c + (g + 1) * 9216;
      if (g & 1) { CPA_B(sm_b0, src, 96, 0) }
      else       { CPA_B(sm_b1, src, 96, 0) }
      CP_COMMIT;
    }
    if (g < 3) { CP_WAIT(1); } else { CP_WAIT(0); }
    __syncthreads();
    if (g & 1) { MMA_K96_BF16(sm_b1) } else { MMA_K96_BF16(sm_b0) }
  }
#pragma unroll
  for (int mt = 0; mt < 2; mt++)
#pragma unroll
    for (int nt = 0; nt < 4; nt++) {
      int r0 = row0 + wr * 32 + mt * 16 + gid;
      int c0 = wc * 32 + nt * 8 + 2 * tig;
      float bb0 = b2[c0], bb1 = b2[c0 + 1];
#pragma unroll
      for (int rr = 0; rr < 2; rr++) {
        int i0 = (r0 + rr * 8) * 96 + c0;
        float2 xv = *reinterpret_cast<const float2*>(&g_x1[i0]);
        float2 nv = *reinterpret_cast<const float2*>(&g_n2[i0]);
        *reinterpret_cast<float2*>(&out[i0]) =
            make_float2(xv.x + acc[mt][nt][2 * rr]     + bb0 + nv.x,
                        xv.y + acc[mt][nt][2 * rr + 1] + bb1 + nv.y);
      }
    }
}

extern "C" void kernel_launch(void* const* d_in, const int* in_sizes, int n_in,
                              void* d_out, int out_size) {
  (void)in_sizes; (void)n_in; (void)out_size;
  const float* x    = (const float*)d_in[0];
  const float* Wq   = (const float*)d_in[1];
  const float* Wk   = (const float*)d_in[2];
  const float* Wv   = (const float*)d_in[3];
  const float* Wp   = (const float*)d_in[4];
  const float* bp   = (const float*)d_in[5];
  const float* ln1g = (const float*)d_in[6];
  const float* ln1b = (const float*)d_in[7];
  const float* ln2g = (const float*)d_in[8];
  const float* ln2b = (const float*)d_in[9];
  const float* W1   = (const float*)d_in[10];
  const float* b1   = (const float*)d_in[11];
  const float* W2   = (const float*)d_in[12];
  const float* b2   = (const float*)d_in[13];
  float* out = (float*)d_out;

  unsigned nk1_0, nk1_1, nk2_0, nk2_1;
  tf2x32(0u, 42u, 0u, 0u, nk1_0, nk1_1);
  tf2x32(0u, 42u, 0u, 1u, nk2_0, nk2_1);

  cudaFuncSetAttribute(qkv_kernel,  cudaFuncAttributeMaxDynamicSharedMemorySize, SMEM_BYTES);
  cudaFuncSetAttribute(proj_kernel, cudaFuncAttributeMaxDynamicSharedMemorySize, SMEM_BYTES);
  cudaFuncSetAttribute(ff1_kernel,  cudaFuncAttributeMaxDynamicSharedMemorySize, SMEM_BYTES);
  cudaFuncSetAttribute(ff2_kernel,  cudaFuncAttributeMaxDynamicSharedMemorySize, SMEM_BYTES);

  prep_kernel<<<324, 256>>>(Wq, Wk, Wv, Wp, W1, W2);
  qkv_kernel <<<512, 384, SMEM_BYTES>>>(x, ln1g, ln1b);
  attn_kernel<<<1536, 256>>>(nk1_0, nk1_1);
  proj_kernel<<<512, 384, SMEM_BYTES>>>(bp, x);
  ff1_kernel <<<512, 384, SMEM_BYTES>>>(b1, ln2g, ln2b, nk2_0, nk2_1);
  ff2_kernel <<<512, 384, SMEM_BYTES>>>(b2, out);
}

// round 9
// speedup vs baseline: 1.1126x; 1.1126x over previous
#include <cuda_runtime.h>
#include <cuda_bf16.h>
#include <cstdint>

// Problem dims: B=256, T=256, D=96, H=6, E=16, DFF=384
#define NTOK 65536              // B*T

// ---------------- scratch (device globals; no allocations) ----------------
__device__ __nv_bfloat16 g_h [NTOK * 96];    // attn concat output (bf16)
__device__ __nv_bfloat16 g_q [NTOK * 96];    // [B*H, T, E] bf16
__device__ __nv_bfloat16 g_k [NTOK * 96];
__device__ __nv_bfloat16 g_v [NTOK * 96];
__device__ float         g_x1[NTOK * 96];    // residual after attention branch
__device__ __nv_bfloat16 g_f [NTOK * 384];   // FF hidden (bf16)

// pre-converted bf16 weights (k-major [k][n] layouts)
__device__ __nv_bfloat16 g_wq[96 * 96];
__device__ __nv_bfloat16 g_wk[96 * 96];
__device__ __nv_bfloat16 g_wv[96 * 96];
__device__ __nv_bfloat16 g_wp[96 * 96];
__device__ __nv_bfloat16 g_w1c[96 * 384];
__device__ __nv_bfloat16 g_w2c[384 * 96];

// ---------------- bf16 mma + ldmatrix + cp.async helpers ----------------
__device__ __forceinline__ void ldsm4(unsigned (&r)[4], unsigned addr) {
  asm volatile("ldmatrix.sync.aligned.m8n8.x4.shared.b16 {%0,%1,%2,%3}, [%4];"
               : "=r"(r[0]), "=r"(r[1]), "=r"(r[2]), "=r"(r[3]) : "r"(addr));
}
__device__ __forceinline__ void ldsm4t(unsigned (&r)[4], unsigned addr) {
  asm volatile("ldmatrix.sync.aligned.m8n8.x4.trans.shared.b16 {%0,%1,%2,%3}, [%4];"
               : "=r"(r[0]), "=r"(r[1]), "=r"(r[2]), "=r"(r[3]) : "r"(addr));
}
__device__ __forceinline__ void mma_bf16(float (&d)[4], const unsigned (&a)[4], unsigned b0, unsigned b1) {
  asm volatile("mma.sync.aligned.m16n8k16.row.col.f32.bf16.bf16.f32 "
               "{%0,%1,%2,%3}, {%4,%5,%6,%7}, {%8,%9}, {%0,%1,%2,%3};"
               : "+f"(d[0]), "+f"(d[1]), "+f"(d[2]), "+f"(d[3])
               : "r"(a[0]), "r"(a[1]), "r"(a[2]), "r"(a[3]), "r"(b0), "r"(b1));
}
__device__ __forceinline__ unsigned s2u(const void* p) {
  return (unsigned)__cvta_generic_to_shared(p);
}
__device__ __forceinline__ void cp16(unsigned dst, const void* src) {
  asm volatile("cp.async.cg.shared.global [%0], [%1], 16;" :: "r"(dst), "l"(src));
}
#define CP_COMMIT asm volatile("cp.async.commit_group;")
#define CP_WAIT(N) asm volatile("cp.async.wait_group %0;" :: "n"(N))
__device__ __forceinline__ unsigned pack_bf2(float lo, float hi) {
  __nv_bfloat162 h = __float22bfloat162_rn(make_float2(lo, hi));
  return *reinterpret_cast<unsigned*>(&h);
}

// ---------------- JAX threefry-2x32 (20 rounds) ----------------
__host__ __device__ __forceinline__ void tf2x32(unsigned k0, unsigned k1,
                                                unsigned x0, unsigned x1,
                                                unsigned &o0, unsigned &o1) {
  unsigned k2 = k0 ^ k1 ^ 0x1BD11BDAu;
  unsigned v0 = x0 + k0, v1 = x1 + k1;
#define TFR(r) { v0 += v1; v1 = (v1 << (r)) | (v1 >> (32 - (r))); v1 ^= v0; }
  TFR(13) TFR(15) TFR(26) TFR(6)   v0 += k1; v1 += k2 + 1u;
  TFR(17) TFR(29) TFR(16) TFR(24)  v0 += k2; v1 += k0 + 2u;
  TFR(13) TFR(15) TFR(26) TFR(6)   v0 += k0; v1 += k1 + 3u;
  TFR(17) TFR(29) TFR(16) TFR(24)  v0 += k1; v1 += k2 + 4u;
  TFR(13) TFR(15) TFR(26) TFR(6)   v0 += k2; v1 += k0 + 5u;
#undef TFR
  o0 = v0; o1 = v1;
}

// Giles (2012) single-precision erfinv: one MUFU log + ~9 fma per path.
// Validated bit-path vs reference in R8: rel_err unchanged at 1.78e-4.
__device__ __forceinline__ float fast_erfinv(float x) {
  float w = -__logf((1.0f - x) * (1.0f + x));
  float p;
  if (w < 5.0f) {
    w -= 2.5f;
    p = 2.81022636e-08f;
    p = fmaf(p, w, 3.43273939e-07f);
    p = fmaf(p, w, -3.5233877e-06f);
    p = fmaf(p, w, -4.39150654e-06f);
    p = fmaf(p, w, 0.00021858087f);
    p = fmaf(p, w, -0.00125372503f);
    p = fmaf(p, w, -0.00417768164f);
    p = fmaf(p, w, 0.246640727f);
    p = fmaf(p, w, 1.50140941f);
  } else {
    w = sqrtf(w) - 3.0f;
    p = -0.000200214257f;
    p = fmaf(p, w, 0.000100950558f);
    p = fmaf(p, w, 0.00134934322f);
    p = fmaf(p, w, -0.00367342844f);
    p = fmaf(p, w, 0.00573950773f);
    p = fmaf(p, w, -0.0076224613f);
    p = fmaf(p, w, 0.00943887047f);
    p = fmaf(p, w, 1.00167406f);
    p = fmaf(p, w, 2.83297682f);
  }
  return p * x;
}

__device__ __forceinline__ float jax_noise(unsigned k0, unsigned k1, unsigned idx) {
  unsigned o0, o1;
  tf2x32(k0, k1, 0u, idx, o0, o1);
  unsigned bits = o0 ^ o1;
  float u = __uint_as_float((bits >> 9) | 0x3f800000u) - 1.0f;
  const float lo = -0.99999994f;
  float val = u * 1.99999994f + lo;
  val = fmaxf(lo, val);
  return 0.1f * (1.4142135381698608f * fast_erfinv(val));
}

// ---------------- weight prep: fp32 -> bf16, gather into [k][n] ----------------
__global__ void __launch_bounds__(256) prep_kernel(const float* __restrict__ Wq,
                                                   const float* __restrict__ Wk,
                                                   const float* __restrict__ Wv,
                                                   const float* __restrict__ Wp,
                                                   const float* __restrict__ W1,
                                                   const float* __restrict__ W2) {
  int i = blockIdx.x * 256 + threadIdx.x;
  if (i < 9216) {
    int r = i / 96, c = i % 96;
    int h = c >> 4, e = c & 15;
    int s = h * 1536 + r * 16 + e;
    g_wq[i] = __float2bfloat16_rn(Wq[s]);
    g_wk[i] = __float2bfloat16_rn(Wk[s]);
    g_wv[i] = __float2bfloat16_rn(Wv[s]);
    g_wp[i] = __float2bfloat16_rn(Wp[i]);
  } else if (i < 9216 + 36864) {
    int j = i - 9216;
    g_w1c[j] = __float2bfloat16_rn(W1[j]);
  } else if (i < 9216 + 2 * 36864) {
    int j = i - 9216 - 36864;
    g_w2c[j] = __float2bfloat16_rn(W2[j]);
  }
}

// ============ smem: A 128x96 bf16 stride 136; B double-buffered 96x96 ============
#define SASTRIDE 136
#define A_ELEMS (128 * SASTRIDE)
#define B_ELEMS (96 * SASTRIDE)
#define SMEM_BYTES ((A_ELEMS + 2 * B_ELEMS) * 2)

#define GEMM_PROLOG \
  extern __shared__ __align__(16) char smraw[]; \
  __nv_bfloat16* sm_a  = reinterpret_cast<__nv_bfloat16*>(smraw); \
  __nv_bfloat16* sm_b0 = sm_a + A_ELEMS; \
  __nv_bfloat16* sm_b1 = sm_b0 + B_ELEMS; \
  int tid = threadIdx.x; \
  int warp = tid >> 5, lane = tid & 31; \
  int wr = warp / 3, wc = warp % 3; \
  int gid = lane >> 2, tig = lane & 3; \
  int lrow = lane & 15, lsel = lane >> 4; \
  int row0 = blockIdx.x * 128; \
  unsigned aB0 = s2u(&sm_a[(wr * 32 + lrow) * SASTRIDE + lsel * 8]); \
  unsigned aB1 = aB0 + 16 * SASTRIDE * 2;

#define CPA_B(BUF, SRC, LD, OFF) \
  _Pragma("unroll") \
  for (int i = 0; i < 3; i++) { \
    int c = tid + i * 384; int r = c / 12, q = c % 12; \
    cp16(s2u(&(BUF)[r * SASTRIDE + q * 8]), (SRC) + r * (LD) + (OFF) + q * 8); \
  }

#define CPA_A(SRC, LD, OFF) \
  _Pragma("unroll") \
  for (int i = 0; i < 4; i++) { \
    int c = tid + i * 384; int r = c / 12, q = c % 12; \
    cp16(s2u(&sm_a[r * SASTRIDE + q * 8]), (SRC) + (size_t)(row0 + r) * (LD) + (OFF) + q * 8); \
  }

#define LN_TO_SMEM(SRC, G, Bv) \
  { \
    float g0 = (G)[lane], g1 = (G)[lane + 32], g2 = (G)[lane + 64]; \
    float b0 = (Bv)[lane], b1 = (Bv)[lane + 32], b2 = (Bv)[lane + 64]; \
    for (int r = warp; r < 128; r += 12) { \
      const float* xr = (SRC) + (size_t)(row0 + r) * 96; \
      float v0 = xr[lane], v1 = xr[lane + 32], v2 = xr[lane + 64]; \
      float s = v0 + v1 + v2, sq = v0 * v0 + v1 * v1 + v2 * v2; \
      _Pragma("unroll") \
      for (int o = 16; o; o >>= 1) { \
        s  += __shfl_xor_sync(0xffffffffu, s, o); \
        sq += __shfl_xor_sync(0xffffffffu, sq, o); \
      } \
      float mu = s * (1.0f / 96.0f); \
      float rs = rsqrtf(sq * (1.0f / 96.0f) - mu * mu + 1e-5f); \
      sm_a[r * SASTRIDE + lane]      = __float2bfloat16_rn((v0 - mu) * rs * g0 + b0); \
      sm_a[r * SASTRIDE + lane + 32] = __float2bfloat16_rn((v1 - mu) * rs * g1 + b1); \
      sm_a[r * SASTRIDE + lane + 64] = __float2bfloat16_rn((v2 - mu) * rs * g2 + b2); \
    } \
  }

#define MMA_K96_BF16(BB) \
  { \
    unsigned bb0 = s2u(&(BB)[lrow * SASTRIDE + wc * 32 + lsel * 8]); \
    unsigned bb1 = bb0 + 16 * 2; \
    _Pragma("unroll") \
    for (int kc = 0; kc < 6; kc++) { \
      unsigned a[2][4], bt[2][4]; \
      ldsm4 (a[0],  aB0 + kc * 32); \
      ldsm4 (a[1],  aB1 + kc * 32); \
      ldsm4t(bt[0], bb0 + kc * (16 * SASTRIDE * 2)); \
      ldsm4t(bt[1], bb1 + kc * (16 * SASTRIDE * 2)); \
      _Pragma("unroll") \
      for (int mt = 0; mt < 2; mt++) \
        _Pragma("unroll") \
        for (int nt = 0; nt < 4; nt++) \
          mma_bf16(acc[mt][nt], a[mt], bt[nt >> 1][(nt & 1) * 2], bt[nt >> 1][(nt & 1) * 2 + 1]); \
    } \
  }

// ---- fused LN1 + QKV: B tiles double-buffered; bf16 q/k/v out ----
__global__ void __launch_bounds__(384, 2) qkv_kernel(const float* __restrict__ x,
                                                     const float* __restrict__ ln1g,
                                                     const float* __restrict__ ln1b) {
  GEMM_PROLOG
  CPA_B(sm_b0, g_wq, 96, 0)
  CP_COMMIT;
  LN_TO_SMEM(x, ln1g, ln1b)
  for (int w = 0; w < 3; w++) {
    CP_WAIT(0);
    __syncthreads();
    if (w == 0) { CPA_B(sm_b1, g_wk, 96, 0) CP_COMMIT; }
    if (w == 1) { CPA_B(sm_b0, g_wv, 96, 0) CP_COMMIT; }
    float acc[2][4][4] = {};
    if (w & 1) { MMA_K96_BF16(sm_b1) } else { MMA_K96_BF16(sm_b0) }
    __nv_bfloat16* Out = (w == 0) ? g_q : (w == 1) ? g_k : g_v;
#pragma unroll
    for (int mt = 0; mt < 2; mt++)
#pragma unroll
      for (int nt = 0; nt < 4; nt++) {
        int r0 = row0 + wr * 32 + mt * 16 + gid;
        int c0 = wc * 32 + nt * 8 + 2 * tig;
        int h = c0 >> 4, e = c0 & 15;
#pragma unroll
        for (int rr = 0; rr < 2; rr++) {
          int tok = r0 + rr * 8;
          int b_ = tok >> 8, t_ = tok & 255;
          *reinterpret_cast<__nv_bfloat162*>(&Out[((b_ * 6 + h) * 256 + t_) * 16 + e]) =
              __float22bfloat162_rn(make_float2(acc[mt][nt][2 * rr], acc[mt][nt][2 * rr + 1]));
        }
      }
  }
}

// ---- tensor-core flash attention ----
__global__ void __launch_bounds__(256) attn_kernel() {
  int bh = blockIdx.x;
  __shared__ __align__(16) __nv_bfloat16 qs[256 * 24];
  __shared__ __align__(16) __nv_bfloat16 ks[256 * 24];
  __shared__ __align__(16) __nv_bfloat16 vs[256 * 24];
  const __nv_bfloat16* qb = g_q + (size_t)bh * 4096;
  const __nv_bfloat16* kb = g_k + (size_t)bh * 4096;
  const __nv_bfloat16* vb = g_v + (size_t)bh * 4096;
  int tid = threadIdx.x;
#pragma unroll
  for (int i = 0; i < 2; i++) {
    int idx = tid + i * 256;
    int r = idx >> 1, half = idx & 1;
    cp16(s2u(&qs[r * 24 + half * 8]), qb + r * 16 + half * 8);
    cp16(s2u(&ks[r * 24 + half * 8]), kb + r * 16 + half * 8);
    cp16(s2u(&vs[r * 24 + half * 8]), vb + r * 16 + half * 8);
  }
  CP_COMMIT;
  CP_WAIT(0);
  __syncthreads();
  int warp = tid >> 5, lane = tid & 31;
  int gid = lane >> 2, tig = lane & 3;
  int lrow = lane & 15, lsel = lane >> 4;
  int r0 = warp * 32;

  unsigned qa[2][4];
  ldsm4(qa[0], s2u(&qs[(r0 + lrow) * 24 + lsel * 8]));
  ldsm4(qa[1], s2u(&qs[(r0 + 16 + lrow) * 24 + lsel * 8]));

  float o[2][2][4] = {};
  float lsum[2][2] = {};
  int krow_off = (lane & 7) + ((lane >> 4) << 3);
  int khalf = (lane >> 3) & 1;
  int nkb = (r0 >> 6) + 1;

  for (int kbk = 0; kbk < nkb; kbk++) {
    int cb = kbk * 64;
    unsigned kf[4][4];
#pragma unroll
    for (int i = 0; i < 4; i++)
      ldsm4(kf[i], s2u(&ks[(cb + i * 16 + krow_off) * 24 + khalf * 8]));
    unsigned pa[2][4][4];
#pragma unroll
    for (int mt = 0; mt < 2; mt++) {
      int ra = r0 + mt * 16 + gid, rb = ra + 8;
      float s[8][4];
#pragma unroll
      for (int nt = 0; nt < 8; nt++) {
        s[nt][0] = s[nt][1] = s[nt][2] = s[nt][3] = 0.0f;
        mma_bf16(s[nt], qa[mt], kf[nt >> 1][(nt & 1) * 2], kf[nt >> 1][(nt & 1) * 2 + 1]);
      }
#pragma unroll
      for (int nt = 0; nt < 8; nt++) {
        int c0 = cb + nt * 8 + 2 * tig;
        float p0 = (c0     <= ra) ? __expf(s[nt][0] * 0.25f) : 0.0f;
        float p1 = (c0 + 1 <= ra) ? __expf(s[nt][1] * 0.25f) : 0.0f;
        float p2 = (c0     <= rb) ? __expf(s[nt][2] * 0.25f) : 0.0f;
        float p3 = (c0 + 1 <= rb) ? __expf(s[nt][3] * 0.25f) : 0.0f;
        lsum[mt][0] += p0 + p1;
        lsum[mt][1] += p2 + p3;
        int kc = nt >> 1, hi = nt & 1;
        pa[mt][kc][hi * 2 + 0] = pack_bf2(p0, p1);
        pa[mt][kc][hi * 2 + 1] = pack_bf2(p2, p3);
      }
    }
#pragma unroll
    for (int kc = 0; kc < 4; kc++) {
      unsigned vt[4];
      ldsm4t(vt, s2u(&vs[(cb + kc * 16 + lrow) * 24 + lsel * 8]));
#pragma unroll
      for (int mt = 0; mt < 2; mt++) {
        mma_bf16(o[mt][0], pa[mt][kc], vt[0], vt[1]);
        mma_bf16(o[mt][1], pa[mt][kc], vt[2], vt[3]);
      }
    }
  }
#pragma unroll
  for (int mt = 0; mt < 2; mt++)
#pragma unroll
    for (int rr = 0; rr < 2; rr++) {
      float v = lsum[mt][rr];
      v += __shfl_xor_sync(0xffffffffu, v, 1);
      v += __shfl_xor_sync(0xffffffffu, v, 2);
      lsum[mt][rr] = 1.0f / v;
    }
  int b_ = bh / 6, h_ = bh % 6;
#pragma unroll
  for (int mt = 0; mt < 2; mt++) {
    int ra = r0 + mt * 16 + gid, rb = ra + 8;
#pragma unroll
    for (int nt = 0; nt < 2; nt++) {
      int c = nt * 8 + 2 * tig;
      *reinterpret_cast<__nv_bfloat162*>(&g_h[((size_t)(b_ * 256 + ra)) * 96 + h_ * 16 + c]) =
          __float22bfloat162_rn(make_float2(o[mt][nt][0] * lsum[mt][0], o[mt][nt][1] * lsum[mt][0]));
      *reinterpret_cast<__nv_bfloat162*>(&g_h[((size_t)(b_ * 256 + rb)) * 96 + h_ * 16 + c]) =
          __float22bfloat162_rn(make_float2(o[mt][nt][2] * lsum[mt][1], o[mt][nt][3] * lsum[mt][1]));
    }
  }
}

// ---- projection + residual + noise1 (fused epilogue) ----
__global__ void __launch_bounds__(384, 2) proj_kernel(const float* __restrict__ bp,
                                                      const float* __restrict__ x,
                                                      unsigned nk0, unsigned nk1v) {
  GEMM_PROLOG
  CPA_A(g_h, 96, 0)
  CPA_B(sm_b0, g_wp, 96, 0)
  CP_COMMIT;
  CP_WAIT(0);
  __syncthreads();
  float acc[2][4][4] = {};
  MMA_K96_BF16(sm_b0)
#pragma unroll
  for (int mt = 0; mt < 2; mt++)
#pragma unroll
    for (int nt = 0; nt < 4; nt++) {
      int r0 = row0 + wr * 32 + mt * 16 + gid;
      int c0 = wc * 32 + nt * 8 + 2 * tig;
      float bp0 = bp[c0], bp1 = bp[c0 + 1];
#pragma unroll
      for (int rr = 0; rr < 2; rr++) {
        int i0 = (r0 + rr * 8) * 96 + c0;
        float2 xv = *reinterpret_cast<const float2*>(&x[i0]);
        *reinterpret_cast<float2*>(&g_x1[i0]) =
            make_float2(xv.x + acc[mt][nt][2 * rr]     + bp0 + jax_noise(nk0, nk1v, (unsigned)i0),
                        xv.y + acc[mt][nt][2 * rr + 1] + bp1 + jax_noise(nk0, nk1v, (unsigned)(i0 + 1)));
      }
    }
}

// ---- fused LN2 + FF1 (4 col groups, B double-buffered) ----
__global__ void __launch_bounds__(384, 2) ff1_kernel(const float* __restrict__ b1,
                                                     const float* __restrict__ ln2g,
                                                     const float* __restrict__ ln2b) {
  GEMM_PROLOG
  CPA_B(sm_b0, g_w1c, 384, 0)
  CP_COMMIT;
  LN_TO_SMEM(g_x1, ln2g, ln2b)
  for (int grp = 0; grp < 4; grp++) {
    int co = grp * 96;
    CP_WAIT(0);
    __syncthreads();
    if (grp < 3) {
      if (grp & 1) { CPA_B(sm_b0, g_w1c, 384, co + 96) }
      else         { CPA_B(sm_b1, g_w1c, 384, co + 96) }
      CP_COMMIT;
    }
    float acc[2][4][4] = {};
    if (grp & 1) { MMA_K96_BF16(sm_b1) } else { MMA_K96_BF16(sm_b0) }
#pragma unroll
    for (int mt = 0; mt < 2; mt++)
#pragma unroll
      for (int nt = 0; nt < 4; nt++) {
        int r0 = row0 + wr * 32 + mt * 16 + gid;
        int c0 = wc * 32 + nt * 8 + 2 * tig;
        float bb0 = b1[co + c0], bb1 = b1[co + c0 + 1];
#pragma unroll
        for (int rr = 0; rr < 2; rr++) {
          int tok = r0 + rr * 8;
          *reinterpret_cast<__nv_bfloat162*>(&g_f[(size_t)tok * 384 + co + c0]) =
              __float22bfloat162_rn(make_float2(fmaxf(acc[mt][nt][2 * rr] + bb0, 0.0f),
                                                fmaxf(acc[mt][nt][2 * rr + 1] + bb1, 0.0f)));
        }
      }
  }
}

// ---- FF2 + residual + noise2 -> out (K=384 in 4 chunks; B pipelined) ----
__global__ void __launch_bounds__(384, 2) ff2_kernel(const float* __restrict__ b2,
                                                     float* __restrict__ out,
                                                     unsigned nk0, unsigned nk1v) {
  GEMM_PROLOG
  CPA_B(sm_b0, g_w2c, 96, 0)
  CP_COMMIT;
  float acc[2][4][4] = {};
#pragma unroll
  for (int g = 0; g < 4; g++) {
    __syncthreads();
    CPA_A(g_f, 384, g * 96)
    CP_COMMIT;
    if (g < 3) {
      const __nv_bfloat16* src = g_w2c + (g + 1) * 9216;
      if (g & 1) { CPA_B(sm_b0, src, 96, 0) }
      else       { CPA_B(sm_b1, src, 96, 0) }
      CP_COMMIT;
    }
    if (g < 3) { CP_WAIT(1); } else { CP_WAIT(0); }
    __syncthreads();
    if (g & 1) { MMA_K96_BF16(sm_b1) } else { MMA_K96_BF16(sm_b0) }
  }
#pragma unroll
  for (int mt = 0; mt < 2; mt++)
#pragma unroll
    for (int nt = 0; nt < 4; nt++) {
      int r0 = row0 + wr * 32 + mt * 16 + gid;
      int c0 = wc * 32 + nt * 8 + 2 * tig;
      float bb0 = b2[c0], bb1 = b2[c0 + 1];
#pragma unroll
      for (int rr = 0; rr < 2; rr++) {
        int i0 = (r0 + rr * 8) * 96 + c0;
        float2 xv = *reinterpret_cast<const float2*>(&g_x1[i0]);
        *reinterpret_cast<float2*>(&out[i0]) =
            make_float2(xv.x + acc[mt][nt][2 * rr]     + bb0 + jax_noise(nk0, nk1v, (unsigned)i0),
                        xv.y + acc[mt][nt][2 * rr + 1] + bb1 + jax_noise(nk0, nk1v, (unsigned)(i0 + 1)));
      }
    }
}

extern "C" void kernel_launch(void* const* d_in, const int* in_sizes, int n_in,
                              void* d_out, int out_size) {
  (void)in_sizes; (void)n_in; (void)out_size;
  const float* x    = (const float*)d_in[0];
  const float* Wq   = (const float*)d_in[1];
  const float* Wk   = (const float*)d_in[2];
  const float* Wv   = (const float*)d_in[3];
  const float* Wp   = (const float*)d_in[4];
  const float* bp   = (const float*)d_in[5];
  const float* ln1g = (const float*)d_in[6];
  const float* ln1b = (const float*)d_in[7];
  const float* ln2g = (const float*)d_in[8];
  const float* ln2b = (const float*)d_in[9];
  const float* W1   = (const float*)d_in[10];
  const float* b1   = (const float*)d_in[11];
  const float* W2   = (const float*)d_in[12];
  const float* b2   = (const float*)d_in[13];
  float* out = (float*)d_out;

  unsigned nk1_0, nk1_1, nk2_0, nk2_1;
  tf2x32(0u, 42u, 0u, 0u, nk1_0, nk1_1);
  tf2x32(0u, 42u, 0u, 1u, nk2_0, nk2_1);

  cudaFuncSetAttribute(qkv_kernel,  cudaFuncAttributeMaxDynamicSharedMemorySize, SMEM_BYTES);
  cudaFuncSetAttribute(proj_kernel, cudaFuncAttributeMaxDynamicSharedMemorySize, SMEM_BYTES);
  cudaFuncSetAttribute(ff1_kernel,  cudaFuncAttributeMaxDynamicSharedMemorySize, SMEM_BYTES);
  cudaFuncSetAttribute(ff2_kernel,  cudaFuncAttributeMaxDynamicSharedMemorySize, SMEM_BYTES);

  prep_kernel<<<324, 256>>>(Wq, Wk, Wv, Wp, W1, W2);
  qkv_kernel <<<512, 384, SMEM_BYTES>>>(x, ln1g, ln1b);
  attn_kernel<<<1536, 256>>>();
  proj_kernel<<<512, 384, SMEM_BYTES>>>(bp, x, nk1_0, nk1_1);
  ff1_kernel <<<512, 384, SMEM_BYTES>>>(b1, ln2g, ln2b);
  ff2_kernel <<<512, 384, SMEM_BYTES>>>(b2, out, nk2_0, nk2_1);
}

// round 10
// speedup vs baseline: 1.3447x; 1.2086x over previous
#include <cuda_runtime.h>
#include <cuda_bf16.h>
#include <cstdint>

// Problem dims: B=256, T=256, D=96, H=6, E=16, DFF=384
#define NTOK 65536              // B*T

// ---------------- scratch (device globals; no allocations) ----------------
__device__ __nv_bfloat16 g_h [NTOK * 96];    // attn concat output (bf16)
__device__ __nv_bfloat16 g_q [NTOK * 96];    // [B*H, T, E] bf16
__device__ __nv_bfloat16 g_k [NTOK * 96];
__device__ __nv_bfloat16 g_v [NTOK * 96];
__device__ float         g_x1[NTOK * 96];    // residual after attention branch

// pre-converted bf16 weights (k-major [k][n] layouts)
__device__ __nv_bfloat16 g_wq[96 * 96];
__device__ __nv_bfloat16 g_wk[96 * 96];
__device__ __nv_bfloat16 g_wv[96 * 96];
__device__ __nv_bfloat16 g_wp[96 * 96];
__device__ __nv_bfloat16 g_w1c[96 * 384];
__device__ __nv_bfloat16 g_w2c[384 * 96];

// ---------------- bf16 mma + ldmatrix + cp.async helpers ----------------
__device__ __forceinline__ void ldsm4(unsigned (&r)[4], unsigned addr) {
  asm volatile("ldmatrix.sync.aligned.m8n8.x4.shared.b16 {%0,%1,%2,%3}, [%4];"
               : "=r"(r[0]), "=r"(r[1]), "=r"(r[2]), "=r"(r[3]) : "r"(addr));
}
__device__ __forceinline__ void ldsm4t(unsigned (&r)[4], unsigned addr) {
  asm volatile("ldmatrix.sync.aligned.m8n8.x4.trans.shared.b16 {%0,%1,%2,%3}, [%4];"
               : "=r"(r[0]), "=r"(r[1]), "=r"(r[2]), "=r"(r[3]) : "r"(addr));
}
__device__ __forceinline__ void mma_bf16(float (&d)[4], const unsigned (&a)[4], unsigned b0, unsigned b1) {
  asm volatile("mma.sync.aligned.m16n8k16.row.col.f32.bf16.bf16.f32 "
               "{%0,%1,%2,%3}, {%4,%5,%6,%7}, {%8,%9}, {%0,%1,%2,%3};"
               : "+f"(d[0]), "+f"(d[1]), "+f"(d[2]), "+f"(d[3])
               : "r"(a[0]), "r"(a[1]), "r"(a[2]), "r"(a[3]), "r"(b0), "r"(b1));
}
__device__ __forceinline__ unsigned s2u(const void* p) {
  return (unsigned)__cvta_generic_to_shared(p);
}
__device__ __forceinline__ void cp16(unsigned dst, const void* src) {
  asm volatile("cp.async.cg.shared.global [%0], [%1], 16;" :: "r"(dst), "l"(src));
}
#define CP_COMMIT asm volatile("cp.async.commit_group;")
#define CP_WAIT(N) asm volatile("cp.async.wait_group %0;" :: "n"(N))
__device__ __forceinline__ unsigned pack_bf2(float lo, float hi) {
  __nv_bfloat162 h = __float22bfloat162_rn(make_float2(lo, hi));
  return *reinterpret_cast<unsigned*>(&h);
}

// ---------------- JAX threefry-2x32 (20 rounds) ----------------
__host__ __device__ __forceinline__ void tf2x32(unsigned k0, unsigned k1,
                                                unsigned x0, unsigned x1,
                                                unsigned &o0, unsigned &o1) {
  unsigned k2 = k0 ^ k1 ^ 0x1BD11BDAu;
  unsigned v0 = x0 + k0, v1 = x1 + k1;
#define TFR(r) { v0 += v1; v1 = (v1 << (r)) | (v1 >> (32 - (r))); v1 ^= v0; }
  TFR(13) TFR(15) TFR(26) TFR(6)   v0 += k1; v1 += k2 + 1u;
  TFR(17) TFR(29) TFR(16) TFR(24)  v0 += k2; v1 += k0 + 2u;
  TFR(13) TFR(15) TFR(26) TFR(6)   v0 += k0; v1 += k1 + 3u;
  TFR(17) TFR(29) TFR(16) TFR(24)  v0 += k1; v1 += k2 + 4u;
  TFR(13) TFR(15) TFR(26) TFR(6)   v0 += k2; v1 += k0 + 5u;
#undef TFR
  o0 = v0; o1 = v1;
}

__device__ __forceinline__ float jax_noise(unsigned k0, unsigned k1, unsigned idx) {
  unsigned o0, o1;
  tf2x32(k0, k1, 0u, idx, o0, o1);
  unsigned bits = o0 ^ o1;
  float u = __uint_as_float((bits >> 9) | 0x3f800000u) - 1.0f;
  const float lo = -0.99999994f;
  float val = u * 1.99999994f + lo;
  val = fmaxf(lo, val);
  return 0.1f * (1.4142135381698608f * erfinvf(val));
}

// ---------------- weight prep: fp32 -> bf16, gather into [k][n] ----------------
__global__ void __launch_bounds__(256) prep_kernel(const float* __restrict__ Wq,
                                                   const float* __restrict__ Wk,
                                                   const float* __restrict__ Wv,
                                                   const float* __restrict__ Wp,
                                                   const float* __restrict__ W1,
                                                   const float* __restrict__ W2) {
  int i = blockIdx.x * 256 + threadIdx.x;
  if (i < 9216) {
    int r = i / 96, c = i % 96;
    int h = c >> 4, e = c & 15;
    int s = h * 1536 + r * 16 + e;
    g_wq[i] = __float2bfloat16_rn(Wq[s]);
    g_wk[i] = __float2bfloat16_rn(Wk[s]);
    g_wv[i] = __float2bfloat16_rn(Wv[s]);
    g_wp[i] = __float2bfloat16_rn(Wp[i]);
  } else if (i < 9216 + 36864) {
    int j = i - 9216;
    g_w1c[j] = __float2bfloat16_rn(W1[j]);
  } else if (i < 9216 + 2 * 36864) {
    int j = i - 9216 - 36864;
    g_w2c[j] = __float2bfloat16_rn(W2[j]);
  }
}

// ============ smem geometry ============
#define SASTRIDE 136                     // 68 words ≡ 4 mod 32: conflict-free ldsm
#define FSTRIDE  392                     // 196 words ≡ 4 mod 32: conflict-free ldsm
#define A_ELEMS (128 * SASTRIDE)
#define B_ELEMS (96 * SASTRIDE)
#define F_ELEMS (128 * FSTRIDE)
#define SMEM_BYTES    ((A_ELEMS + 2 * B_ELEMS) * 2)
#define FF_SMEM_BYTES ((A_ELEMS + F_ELEMS + 2 * B_ELEMS) * 2)

#define GEMM_PROLOG \
  extern __shared__ __align__(16) char smraw[]; \
  __nv_bfloat16* sm_a  = reinterpret_cast<__nv_bfloat16*>(smraw); \
  __nv_bfloat16* sm_b0 = sm_a + A_ELEMS; \
  __nv_bfloat16* sm_b1 = sm_b0 + B_ELEMS; \
  int tid = threadIdx.x; \
  int warp = tid >> 5, lane = tid & 31; \
  int wr = warp / 3, wc = warp % 3; \
  int gid = lane >> 2, tig = lane & 3; \
  int lrow = lane & 15, lsel = lane >> 4; \
  int row0 = blockIdx.x * 128; \
  unsigned aB0 = s2u(&sm_a[(wr * 32 + lrow) * SASTRIDE + lsel * 8]); \
  unsigned aB1 = aB0 + 16 * SASTRIDE * 2;

#define CPA_B(BUF, SRC, LD, OFF) \
  _Pragma("unroll") \
  for (int i = 0; i < 3; i++) { \
    int c = tid + i * 384; int r = c / 12, q = c % 12; \
    cp16(s2u(&(BUF)[r * SASTRIDE + q * 8]), (SRC) + r * (LD) + (OFF) + q * 8); \
  }

#define CPA_A(SRC, LD, OFF) \
  _Pragma("unroll") \
  for (int i = 0; i < 4; i++) { \
    int c = tid + i * 384; int r = c / 12, q = c % 12; \
    cp16(s2u(&sm_a[r * SASTRIDE + q * 8]), (SRC) + (size_t)(row0 + r) * (LD) + (OFF) + q * 8); \
  }

#define LN_TO_SMEM(SRC, G, Bv, NW) \
  { \
    float g0 = (G)[lane], g1 = (G)[lane + 32], g2 = (G)[lane + 64]; \
    float b0 = (Bv)[lane], b1 = (Bv)[lane + 32], b2 = (Bv)[lane + 64]; \
    for (int r = warp; r < 128; r += (NW)) { \
      const float* xr = (SRC) + (size_t)(row0 + r) * 96; \
      float v0 = xr[lane], v1 = xr[lane + 32], v2 = xr[lane + 64]; \
      float s = v0 + v1 + v2, sq = v0 * v0 + v1 * v1 + v2 * v2; \
      _Pragma("unroll") \
      for (int o = 16; o; o >>= 1) { \
        s  += __shfl_xor_sync(0xffffffffu, s, o); \
        sq += __shfl_xor_sync(0xffffffffu, sq, o); \
      } \
      float mu = s * (1.0f / 96.0f); \
      float rs = rsqrtf(sq * (1.0f / 96.0f) - mu * mu + 1e-5f); \
      sm_a[r * SASTRIDE + lane]      = __float2bfloat16_rn((v0 - mu) * rs * g0 + b0); \
      sm_a[r * SASTRIDE + lane + 32] = __float2bfloat16_rn((v1 - mu) * rs * g1 + b1); \
      sm_a[r * SASTRIDE + lane + 64] = __float2bfloat16_rn((v2 - mu) * rs * g2 + b2); \
    } \
  }

// MMA over K=96: A fragments from (AB0,AB1) with byte offset KOFF, B tile BB.
#define MMA_K96_GEN(BB, AB0, AB1, KOFF, ACC) \
  { \
    unsigned bb0 = s2u(&(BB)[lrow * SASTRIDE + wc * 32 + lsel * 8]); \
    unsigned bb1 = bb0 + 16 * 2; \
    _Pragma("unroll") \
    for (int kc = 0; kc < 6; kc++) { \
      unsigned a[2][4], bt[2][4]; \
      ldsm4 (a[0],  (AB0) + (KOFF) + kc * 32); \
      ldsm4 (a[1],  (AB1) + (KOFF) + kc * 32); \
      ldsm4t(bt[0], bb0 + kc * (16 * SASTRIDE * 2)); \
      ldsm4t(bt[1], bb1 + kc * (16 * SASTRIDE * 2)); \
      _Pragma("unroll") \
      for (int mt = 0; mt < 2; mt++) \
        _Pragma("unroll") \
        for (int nt = 0; nt < 4; nt++) \
          mma_bf16(ACC[mt][nt], a[mt], bt[nt >> 1][(nt & 1) * 2], bt[nt >> 1][(nt & 1) * 2 + 1]); \
    } \
  }
#define MMA_K96_BF16(BB) MMA_K96_GEN(BB, aB0, aB1, 0, acc)

// ---- fused LN1 + QKV: B tiles double-buffered; bf16 q/k/v out ----
__global__ void __launch_bounds__(384, 2) qkv_kernel(const float* __restrict__ x,
                                                     const float* __restrict__ ln1g,
                                                     const float* __restrict__ ln1b) {
  GEMM_PROLOG
  CPA_B(sm_b0, g_wq, 96, 0)
  CP_COMMIT;
  LN_TO_SMEM(x, ln1g, ln1b, 12)
  for (int w = 0; w < 3; w++) {
    CP_WAIT(0);
    __syncthreads();
    if (w == 0) { CPA_B(sm_b1, g_wk, 96, 0) CP_COMMIT; }
    if (w == 1) { CPA_B(sm_b0, g_wv, 96, 0) CP_COMMIT; }
    float acc[2][4][4] = {};
    if (w & 1) { MMA_K96_BF16(sm_b1) } else { MMA_K96_BF16(sm_b0) }
    __nv_bfloat16* Out = (w == 0) ? g_q : (w == 1) ? g_k : g_v;
#pragma unroll
    for (int mt = 0; mt < 2; mt++)
#pragma unroll
      for (int nt = 0; nt < 4; nt++) {
        int r0 = row0 + wr * 32 + mt * 16 + gid;
        int c0 = wc * 32 + nt * 8 + 2 * tig;
        int h = c0 >> 4, e = c0 & 15;
#pragma unroll
        for (int rr = 0; rr < 2; rr++) {
          int tok = r0 + rr * 8;
          int b_ = tok >> 8, t_ = tok & 255;
          *reinterpret_cast<__nv_bfloat162*>(&Out[((b_ * 6 + h) * 256 + t_) * 16 + e]) =
              __float22bfloat162_rn(make_float2(acc[mt][nt][2 * rr], acc[mt][nt][2 * rr + 1]));
        }
      }
  }
}

// ---- tensor-core flash attention (causal mask only on diagonal block) ----
__global__ void __launch_bounds__(256) attn_kernel() {
  int bh = blockIdx.x;
  __shared__ __align__(16) __nv_bfloat16 qs[256 * 24];
  __shared__ __align__(16) __nv_bfloat16 ks[256 * 24];
  __shared__ __align__(16) __nv_bfloat16 vs[256 * 24];
  const __nv_bfloat16* qb = g_q + (size_t)bh * 4096;
  const __nv_bfloat16* kb = g_k + (size_t)bh * 4096;
  const __nv_bfloat16* vb = g_v + (size_t)bh * 4096;
  int tid = threadIdx.x;
#pragma unroll
  for (int i = 0; i < 2; i++) {
    int idx = tid + i * 256;
    int r = idx >> 1, half = idx & 1;
    cp16(s2u(&qs[r * 24 + half * 8]), qb + r * 16 + half * 8);
    cp16(s2u(&ks[r * 24 + half * 8]), kb + r * 16 + half * 8);
    cp16(s2u(&vs[r * 24 + half * 8]), vb + r * 16 + half * 8);
  }
  CP_COMMIT;
  CP_WAIT(0);
  __syncthreads();
  int warp = tid >> 5, lane = tid & 31;
  int gid = lane >> 2, tig = lane & 3;
  int lrow = lane & 15, lsel = lane >> 4;
  int r0 = warp * 32;

  unsigned qa[2][4];
  ldsm4(qa[0], s2u(&qs[(r0 + lrow) * 24 + lsel * 8]));
  ldsm4(qa[1], s2u(&qs[(r0 + 16 + lrow) * 24 + lsel * 8]));

  float o[2][2][4] = {};
  float lsum[2][2] = {};
  int krow_off = (lane & 7) + ((lane >> 4) << 3);
  int khalf = (lane >> 3) & 1;
  int nkb = (r0 >> 6) + 1;

  for (int kbk = 0; kbk < nkb; kbk++) {
    int cb = kbk * 64;
    bool diag = (kbk == nkb - 1);
    unsigned kf[4][4];
#pragma unroll
    for (int i = 0; i < 4; i++)
      ldsm4(kf[i], s2u(&ks[(cb + i * 16 + krow_off) * 24 + khalf * 8]));
    unsigned pa[2][4][4];
#pragma unroll
    for (int mt = 0; mt < 2; mt++) {
      int ra = r0 + mt * 16 + gid, rb = ra + 8;
      float s[8][4];
#pragma unroll
      for (int nt = 0; nt < 8; nt++) {
        s[nt][0] = s[nt][1] = s[nt][2] = s[nt][3] = 0.0f;
        mma_bf16(s[nt], qa[mt], kf[nt >> 1][(nt & 1) * 2], kf[nt >> 1][(nt & 1) * 2 + 1]);
      }
      if (diag) {
#pragma unroll
        for (int nt = 0; nt < 8; nt++) {
          int c0 = cb + nt * 8 + 2 * tig;
          float p0 = (c0     <= ra) ? __expf(s[nt][0] * 0.25f) : 0.0f;
          float p1 = (c0 + 1 <= ra) ? __expf(s[nt][1] * 0.25f) : 0.0f;
          float p2 = (c0     <= rb) ? __expf(s[nt][2] * 0.25f) : 0.0f;
          float p3 = (c0 + 1 <= rb) ? __expf(s[nt][3] * 0.25f) : 0.0f;
          lsum[mt][0] += p0 + p1;
          lsum[mt][1] += p2 + p3;
          int kc = nt >> 1, hi = nt & 1;
          pa[mt][kc][hi * 2 + 0] = pack_bf2(p0, p1);
          pa[mt][kc][hi * 2 + 1] = pack_bf2(p2, p3);
        }
      } else {
#pragma unroll
        for (int nt = 0; nt < 8; nt++) {
          float p0 = __expf(s[nt][0] * 0.25f);
          float p1 = __expf(s[nt][1] * 0.25f);
          float p2 = __expf(s[nt][2] * 0.25f);
          float p3 = __expf(s[nt][3] * 0.25f);
          lsum[mt][0] += p0 + p1;
          lsum[mt][1] += p2 + p3;
          int kc = nt >> 1, hi = nt & 1;
          pa[mt][kc][hi * 2 + 0] = pack_bf2(p0, p1);
          pa[mt][kc][hi * 2 + 1] = pack_bf2(p2, p3);
        }
      }
    }
#pragma unroll
    for (int kc = 0; kc < 4; kc++) {
      unsigned vt[4];
      ldsm4t(vt, s2u(&vs[(cb + kc * 16 + lrow) * 24 + lsel * 8]));
#pragma unroll
      for (int mt = 0; mt < 2; mt++) {
        mma_bf16(o[mt][0], pa[mt][kc], vt[0], vt[1]);
        mma_bf16(o[mt][1], pa[mt][kc], vt[2], vt[3]);
      }
    }
  }
#pragma unroll
  for (int mt = 0; mt < 2; mt++)
#pragma unroll
    for (int rr = 0; rr < 2; rr++) {
      float v = lsum[mt][rr];
      v += __shfl_xor_sync(0xffffffffu, v, 1);
      v += __shfl_xor_sync(0xffffffffu, v, 2);
      lsum[mt][rr] = 1.0f / v;
    }
  int b_ = bh / 6, h_ = bh % 6;
#pragma unroll
  for (int mt = 0; mt < 2; mt++) {
    int ra = r0 + mt * 16 + gid, rb = ra + 8;
#pragma unroll
    for (int nt = 0; nt < 2; nt++) {
      int c = nt * 8 + 2 * tig;
      *reinterpret_cast<__nv_bfloat162*>(&g_h[((size_t)(b_ * 256 + ra)) * 96 + h_ * 16 + c]) =
          __float22bfloat162_rn(make_float2(o[mt][nt][0] * lsum[mt][0], o[mt][nt][1] * lsum[mt][0]));
      *reinterpret_cast<__nv_bfloat162*>(&g_h[((size_t)(b_ * 256 + rb)) * 96 + h_ * 16 + c]) =
          __float22bfloat162_rn(make_float2(o[mt][nt][2] * lsum[mt][1], o[mt][nt][3] * lsum[mt][1]));
    }
  }
}

// ---- projection + residual + noise1 (fused epilogue) ----
__global__ void __launch_bounds__(384, 2) proj_kernel(const float* __restrict__ bp,
                                                      const float* __restrict__ x,
                                                      unsigned nk0, unsigned nk1v) {
  GEMM_PROLOG
  CPA_A(g_h, 96, 0)
  CPA_B(sm_b0, g_wp, 96, 0)
  CP_COMMIT;
  CP_WAIT(0);
  __syncthreads();
  float acc[2][4][4] = {};
  MMA_K96_BF16(sm_b0)
#pragma unroll
  for (int mt = 0; mt < 2; mt++)
#pragma unroll
    for (int nt = 0; nt < 4; nt++) {
      int r0 = row0 + wr * 32 + mt * 16 + gid;
      int c0 = wc * 32 + nt * 8 + 2 * tig;
      float bp0 = bp[c0], bp1 = bp[c0 + 1];
#pragma unroll
      for (int rr = 0; rr < 2; rr++) {
        int i0 = (r0 + rr * 8) * 96 + c0;
        float2 xv = *reinterpret_cast<const float2*>(&x[i0]);
        *reinterpret_cast<float2*>(&g_x1[i0]) =
            make_float2(xv.x + acc[mt][nt][2 * rr]     + bp0 + jax_noise(nk0, nk1v, (unsigned)i0),
                        xv.y + acc[mt][nt][2 * rr + 1] + bp1 + jax_noise(nk0, nk1v, (unsigned)(i0 + 1)));
      }
    }
}

// ---- fused LN2 + FF1 + FF2 + residual + noise2 -> out ----
// F tile (128x384 bf16) lives in smem; 8 B tiles stream through a double buffer.
__global__ void __launch_bounds__(384, 1) ff_kernel(const float* __restrict__ b1,
                                                    const float* __restrict__ b2,
                                                    const float* __restrict__ ln2g,
                                                    const float* __restrict__ ln2b,
                                                    float* __restrict__ out,
                                                    unsigned nk0, unsigned nk1v) {
  extern __shared__ __align__(16) char smraw[];
  __nv_bfloat16* sm_a  = reinterpret_cast<__nv_bfloat16*>(smraw);
  __nv_bfloat16* sm_f  = sm_a + A_ELEMS;
  __nv_bfloat16* sm_b0 = sm_f + F_ELEMS;
  __nv_bfloat16* sm_b1 = sm_b0 + B_ELEMS;
  int tid = threadIdx.x;
  int warp = tid >> 5, lane = tid & 31;
  int wr = warp / 3, wc = warp % 3;
  int gid = lane >> 2, tig = lane & 3;
  int lrow = lane & 15, lsel = lane >> 4;
  int row0 = blockIdx.x * 128;
  unsigned aB0 = s2u(&sm_a[(wr * 32 + lrow) * SASTRIDE + lsel * 8]);
  unsigned aB1 = aB0 + 16 * SASTRIDE * 2;
  unsigned fB0 = s2u(&sm_f[(wr * 32 + lrow) * FSTRIDE + lsel * 8]);
  unsigned fB1 = fB0 + 16 * FSTRIDE * 2;

  CPA_B(sm_b0, g_w1c, 384, 0)
  CP_COMMIT;
  LN_TO_SMEM(g_x1, ln2g, ln2b, 12)

  float acc2[2][4][4] = {};
  for (int t = 0; t < 8; t++) {
    CP_WAIT(0);
    __syncthreads();
    if (t < 7) {
      int tn = t + 1;
      const __nv_bfloat16* src = (tn < 4) ? g_w1c : (g_w2c + (tn - 4) * 9216);
      int ld  = (tn < 4) ? 384 : 96;
      int off = (tn < 4) ? tn * 96 : 0;
      if (tn & 1) { CPA_B(sm_b1, src, ld, off) } else { CPA_B(sm_b0, src, ld, off) }
      CP_COMMIT;
    }
    if (t < 4) {
      // FF1 group t: A(sm_a) x W1[:, t*96 : t*96+96] -> relu -> sm_f
      float acc[2][4][4] = {};
      if (t & 1) { MMA_K96_GEN(sm_b1, aB0, aB1, 0, acc) }
      else       { MMA_K96_GEN(sm_b0, aB0, aB1, 0, acc) }
      int co = t * 96;
#pragma unroll
      for (int mt = 0; mt < 2; mt++)
#pragma unroll
        for (int nt = 0; nt < 4; nt++) {
          int c0 = wc * 32 + nt * 8 + 2 * tig;
          float bb0 = b1[co + c0], bb1 = b1[co + c0 + 1];
#pragma unroll
          for (int rr = 0; rr < 2; rr++) {
            int rl = wr * 32 + mt * 16 + gid + rr * 8;
            *reinterpret_cast<__nv_bfloat162*>(&sm_f[rl * FSTRIDE + co + c0]) =
                __float22bfloat162_rn(make_float2(fmaxf(acc[mt][nt][2 * rr] + bb0, 0.0f),
                                                  fmaxf(acc[mt][nt][2 * rr + 1] + bb1, 0.0f)));
          }
        }
    } else {
      // FF2 chunk t-4: F[:, g*96 : g*96+96] x W2[g*96 : g*96+96, :] accumulate
      int goff = (t - 4) * 192;   // byte offset into F rows (96 bf16)
      if (t & 1) { MMA_K96_GEN(sm_b1, fB0, fB1, goff, acc2) }
      else       { MMA_K96_GEN(sm_b0, fB0, fB1, goff, acc2) }
    }
  }
#pragma unroll
  for (int mt = 0; mt < 2; mt++)
#pragma unroll
    for (int nt = 0; nt < 4; nt++) {
      int r0 = row0 + wr * 32 + mt * 16 + gid;
      int c0 = wc * 32 + nt * 8 + 2 * tig;
      float bb0 = b2[c0], bb1 = b2[c0 + 1];
#pragma unroll
      for (int rr = 0; rr < 2; rr++) {
        int i0 = (r0 + rr * 8) * 96 + c0;
        float2 xv = *reinterpret_cast<const float2*>(&g_x1[i0]);
        *reinterpret_cast<float2*>(&out[i0]) =
            make_float2(xv.x + acc2[mt][nt][2 * rr]     + bb0 + jax_noise(nk0, nk1v, (unsigned)i0),
                        xv.y + acc2[mt][nt][2 * rr + 1] + bb1 + jax_noise(nk0, nk1v, (unsigned)(i0 + 1)));
      }
    }
}

extern "C" void kernel_launch(void* const* d_in, const int* in_sizes, int n_in,
                              void* d_out, int out_size) {
  (void)in_sizes; (void)n_in; (void)out_size;
  const float* x    = (const float*)d_in[0];
  const float* Wq   = (const float*)d_in[1];
  const float* Wk   = (const float*)d_in[2];
  const float* Wv   = (const float*)d_in[3];
  const float* Wp   = (const float*)d_in[4];
  const float* bp   = (const float*)d_in[5];
  const float* ln1g = (const float*)d_in[6];
  const float* ln1b = (const float*)d_in[7];
  const float* ln2g = (const float*)d_in[8];
  const float* ln2b = (const float*)d_in[9];
  const float* W1   = (const float*)d_in[10];
  const float* b1   = (const float*)d_in[11];
  const float* W2   = (const float*)d_in[12];
  const float* b2   = (const float*)d_in[13];
  float* out = (float*)d_out;

  unsigned nk1_0, nk1_1, nk2_0, nk2_1;
  tf2x32(0u, 42u, 0u, 0u, nk1_0, nk1_1);
  tf2x32(0u, 42u, 0u, 1u, nk2_0, nk2_1);

  cudaFuncSetAttribute(qkv_kernel,  cudaFuncAttributeMaxDynamicSharedMemorySize, SMEM_BYTES);
  cudaFuncSetAttribute(proj_kernel, cudaFuncAttributeMaxDynamicSharedMemorySize, SMEM_BYTES);
  cudaFuncSetAttribute(ff_kernel,   cudaFuncAttributeMaxDynamicSharedMemorySize, FF_SMEM_BYTES);

  prep_kernel<<<324, 256>>>(Wq, Wk, Wv, Wp, W1, W2);
  qkv_kernel <<<512, 384, SMEM_BYTES>>>(x, ln1g, ln1b);
  attn_kernel<<<1536, 256>>>();
  proj_kernel<<<512, 384, SMEM_BYTES>>>(bp, x, nk1_0, nk1_1);
  ff_kernel  <<<512, 384, FF_SMEM_BYTES>>>(b1, b2, ln2g, ln2b, out, nk2_0, nk2_1);
}